// round 5
// baseline (speedup 1.0000x reference)
#include <cuda_runtime.h>
#include <cuda_bf16.h>
#include <math.h>
#include <stdint.h>

// ---------------- problem constants ----------------
#define BB 16
#define TT 256
#define DD 512
#define LL1 51
#define MM (BB*TT)            // 4096
#define LL2 (LL1*LL1)         // 2601
#define KP 1536               // split-K: [x_hi | x_hi | x_lo] * [W_hi ; W_lo ; W_hi]
#define KC 64
#define NCH (KP/KC)           // 24
#define LOG2PI 1.8378770664093453f

// planar output layout (offsets multiples of 128)
#define NP_CH  2688
#define PS_W   0
#define PS_MU  128
#define PS_VAR 256
#define PT_W   384
#define PT_MU0 (PT_W  + NP_CH)   // 3072
#define PT_MU1 (PT_MU0 + NP_CH)  // 5760
#define PT_D0  (PT_MU1 + NP_CH)  // 8448
#define PT_SUM (PT_D0 + NP_CH)   // 11136
#define PT_D1  (PT_SUM + NP_CH)  // 13824
#define NTOT   (PT_D1 + NP_CH)   // 16512 (logical)
#define NTOTP  16640             // padded to 65 tiles of 256
#define NTILES 65

// ---------------- scratch (device globals) ----------------
__device__ __align__(256) __nv_bfloat16 g_Ap[(size_t)MM*KP];
__device__ __align__(256) __nv_bfloat16 g_Bp[(size_t)NTOTP*KP];   // pad rows stay zero (static init)
__device__ __align__(256) float g_bias[NTOTP];
__device__ __align__(256) float g_C[(size_t)MM*NTOTP];

// ---------------- PTX helpers ----------------
__device__ __forceinline__ uint32_t smem_u32(const void* p) {
    uint32_t a;
    asm("{ .reg .u64 t; cvta.to.shared.u64 t, %1; cvt.u32.u64 %0, t; }" : "=r"(a) : "l"(p));
    return a;
}
__device__ __forceinline__ void cp_async16(uint32_t dst, const void* src) {
    asm volatile("cp.async.cg.shared.global [%0], [%1], 16;" :: "r"(dst), "l"(src));
}
#define CP_COMMIT() asm volatile("cp.async.commit_group;" ::: "memory")
#define CP_WAIT(n)  asm volatile("cp.async.wait_group %0;" :: "n"(n) : "memory")

__device__ __forceinline__ void ldmx4(uint32_t* r, uint32_t addr) {
    asm volatile("ldmatrix.sync.aligned.m8n8.x4.shared.b16 {%0,%1,%2,%3}, [%4];"
        : "=r"(r[0]), "=r"(r[1]), "=r"(r[2]), "=r"(r[3]) : "r"(addr));
}
__device__ __forceinline__ void mma16816(float* c, const uint32_t* a, uint32_t b0, uint32_t b1) {
    asm volatile("mma.sync.aligned.m16n8k16.row.col.f32.bf16.bf16.f32 "
        "{%0,%1,%2,%3}, {%4,%5,%6,%7}, {%8,%9}, {%0,%1,%2,%3};"
        : "+f"(c[0]), "+f"(c[1]), "+f"(c[2]), "+f"(c[3])
        : "r"(a[0]), "r"(a[1]), "r"(a[2]), "r"(a[3]), "r"(b0), "r"(b1));
}

// ---------------- fused prep: 9 W jobs + x-split + bias ----------------
// grid (84, 16, 10), block (32, 8)
__global__ void prep_all(const float* __restrict__ x,
    const float* __restrict__ Ws_w, const float* __restrict__ Ws_mu, const float* __restrict__ Ws_var,
    const float* __restrict__ Wt_w, const float* __restrict__ Wt_mu, const float* __restrict__ Wt_var,
    const float* __restrict__ bsw, const float* __restrict__ bsmu, const float* __restrict__ bsvar,
    const float* __restrict__ btw, const float* __restrict__ btmu, const float* __restrict__ btvar)
{
    int z = blockIdx.z;
    int tx = threadIdx.x, ty = threadIdx.y;
    int tid = ty * 32 + tx;

    if (z == 9) {
        int linb = blockIdx.y * gridDim.x + blockIdx.x;
        int nth  = gridDim.x * gridDim.y * 256;
        int gtid = linb * 256 + tid;
        // x -> [hi | hi | lo]
        for (int t = gtid; t < MM * DD; t += nth) {
            int m = t >> 9;
            int k = t & 511;
            float v = x[t];
            __nv_bfloat16 hi = __float2bfloat16(v);
            __nv_bfloat16 lo = __float2bfloat16(v - __bfloat162float(hi));
            size_t base = (size_t)m * KP + k;
            g_Ap[base]        = hi;
            g_Ap[base + 512]  = hi;
            g_Ap[base + 1024] = lo;
        }
        // bias
        for (int c = gtid; c < NTOTP; c += nth) {
            float v = 0.f;
            if (c < PS_MU)        { if (c < LL1) v = bsw[c]; }
            else if (c < PS_VAR)  { int n = c - PS_MU;  if (n < LL1) v = bsmu[n]; }
            else if (c < PT_W)    { int n = c - PS_VAR; if (n < LL1) v = bsvar[n]; }
            else if (c < PT_MU0)  { int n = c - PT_W;   if (n < LL2) v = btw[n]; }
            else if (c < PT_MU1)  { int n = c - PT_MU0; if (n < LL2) v = btmu[2 * n]; }
            else if (c < PT_D0)   { int n = c - PT_MU1; if (n < LL2) v = btmu[2 * n + 1]; }
            else if (c < PT_SUM)  { int n = c - PT_D0;  if (n < LL2) v = btvar[4 * n]; }
            else if (c < PT_D1)   { int n = c - PT_SUM; if (n < LL2) v = btvar[4 * n + 1] + btvar[4 * n + 2]; }
            else if (c < NTOT)    { int n = c - PT_D1;  if (n < LL2) v = btvar[4 * n + 3]; }
            g_bias[c] = v;
        }
        return;
    }

    const float* W; int srcN, dstOff, nValid, colMul, colAdd, colAdd2, bx;
    switch (z) {
        case 0: W = Ws_w;   srcN = LL1;     dstOff = PS_W;   nValid = LL1; colMul = 1; colAdd = 0; colAdd2 = -1; bx = 4;  break;
        case 1: W = Ws_mu;  srcN = LL1;     dstOff = PS_MU;  nValid = LL1; colMul = 1; colAdd = 0; colAdd2 = -1; bx = 4;  break;
        case 2: W = Ws_var; srcN = LL1;     dstOff = PS_VAR; nValid = LL1; colMul = 1; colAdd = 0; colAdd2 = -1; bx = 4;  break;
        case 3: W = Wt_w;   srcN = LL2;     dstOff = PT_W;   nValid = LL2; colMul = 1; colAdd = 0; colAdd2 = -1; bx = 84; break;
        case 4: W = Wt_mu;  srcN = LL2 * 2; dstOff = PT_MU0; nValid = LL2; colMul = 2; colAdd = 0; colAdd2 = -1; bx = 84; break;
        case 5: W = Wt_mu;  srcN = LL2 * 2; dstOff = PT_MU1; nValid = LL2; colMul = 2; colAdd = 1; colAdd2 = -1; bx = 84; break;
        case 6: W = Wt_var; srcN = LL2 * 4; dstOff = PT_D0;  nValid = LL2; colMul = 4; colAdd = 0; colAdd2 = -1; bx = 84; break;
        case 7: W = Wt_var; srcN = LL2 * 4; dstOff = PT_SUM; nValid = LL2; colMul = 4; colAdd = 1; colAdd2 = 2;  bx = 84; break;
        default:W = Wt_var; srcN = LL2 * 4; dstOff = PT_D1;  nValid = LL2; colMul = 4; colAdd = 3; colAdd2 = -1; bx = 84; break;
    }
    if ((int)blockIdx.x >= bx) return;

    __shared__ float tile[32][33];
    int n = blockIdx.x * 32 + tx;
    #pragma unroll
    for (int i = 0; i < 4; i++) {
        int k = blockIdx.y * 32 + ty + i * 8;
        float v = 0.f;
        if (n < nValid) {
            v = W[(size_t)k * srcN + n * colMul + colAdd];
            if (colAdd2 >= 0) v += W[(size_t)k * srcN + n * colMul + colAdd2];
        }
        tile[ty + i * 8][tx] = v;
    }
    __syncthreads();
    #pragma unroll
    for (int i = 0; i < 4; i++) {
        int n2 = blockIdx.x * 32 + ty + i * 8;
        int k2 = blockIdx.y * 32 + tx;
        float v = tile[tx][ty + i * 8];
        __nv_bfloat16 hi = __float2bfloat16(v);
        __nv_bfloat16 lo = __float2bfloat16(v - __bfloat162float(hi));
        __nv_bfloat16* row = g_Bp + (size_t)(dstOff + n2) * KP;
        row[k2]        = hi;
        row[512 + k2]  = lo;
        row[1024 + k2] = hi;
    }
}

// ---------------- HMMA GEMM: 128x256 CTA, 512 threads, KC=64, 3-stage ------
#define TILE_STRIDE 72                 // bf16 elems per smem row (144 B)
#define A_BYTES 18432                  // 128*144
#define B_BYTES 36864                  // 256*144
#define BUF_BYTES (A_BYTES + B_BYTES)  // 55296
#define SMEM_BYTES (3*BUF_BYTES)       // 165888
#define STG_STRIDE 260

__device__ __forceinline__ void issue_tile(uint32_t dstBase,
                                           const __nv_bfloat16* __restrict__ src,
                                           int row0, int kc, int tid, int rows) {
    for (int i = tid; i < rows * 8; i += 512) {
        int r   = i >> 3;
        int c16 = i & 7;
        uint32_t dst = dstBase + (uint32_t)(r * (TILE_STRIDE * 2) + c16 * 16);
        cp_async16(dst, src + (size_t)(row0 + r) * KP + kc + c16 * 8);
    }
}

__global__ void __launch_bounds__(512, 1) gemm_tc()
{
    extern __shared__ char smem[];
    uint32_t sbase = smem_u32(smem);
    int tid = threadIdx.x, wid = tid >> 5, lane = tid & 31;
    int m0 = blockIdx.x * 128;
    int n0 = blockIdx.y * 256;

    int wm = (wid & 3) * 32;     // 4 warp-rows x 32
    int wn = (wid >> 2) * 64;    // 4 warp-cols x 64
    int lr = lane & 15;
    int lc = (lane >> 4) * 8;

    float acc[2][8][4];
    #pragma unroll
    for (int mi = 0; mi < 2; mi++)
        #pragma unroll
        for (int ni = 0; ni < 8; ni++)
            #pragma unroll
            for (int q = 0; q < 4; q++) acc[mi][ni][q] = 0.f;

    // prologue: chunks 0,1 -> bufs 0,1
    issue_tile(sbase,           g_Ap, m0, 0, tid, 128);
    issue_tile(sbase + A_BYTES, g_Bp, n0, 0, tid, 256);
    CP_COMMIT();
    issue_tile(sbase + BUF_BYTES,           g_Ap, m0, KC, tid, 128);
    issue_tile(sbase + BUF_BYTES + A_BYTES, g_Bp, n0, KC, tid, 256);
    CP_COMMIT();

    for (int c = 0; c < NCH; c++) {
        if (c + 1 < NCH) { CP_WAIT(1); } else { CP_WAIT(0); }
        __syncthreads();                  // single barrier per chunk
        if (c + 2 < NCH) {
            uint32_t nb = sbase + (uint32_t)(((c + 2) % 3) * BUF_BYTES);
            issue_tile(nb,           g_Ap, m0, (c + 2) * KC, tid, 128);
            issue_tile(nb + A_BYTES, g_Bp, n0, (c + 2) * KC, tid, 256);
            CP_COMMIT();
        }
        uint32_t aBase = sbase + (uint32_t)((c % 3) * BUF_BYTES);
        uint32_t bBase = aBase + A_BYTES;
        #pragma unroll
        for (int ks = 0; ks < 4; ks++) {
            uint32_t af[2][4];
            #pragma unroll
            for (int mi = 0; mi < 2; mi++)
                ldmx4(af[mi], aBase + (uint32_t)(((wm + mi * 16 + lr) * TILE_STRIDE
                                                  + ks * 16 + lc) * 2));
            uint32_t bf[4][4];
            #pragma unroll
            for (int nb = 0; nb < 4; nb++)
                ldmx4(bf[nb], bBase + (uint32_t)(((wn + nb * 16 + lr) * TILE_STRIDE
                                                  + ks * 16 + lc) * 2));
            #pragma unroll
            for (int mi = 0; mi < 2; mi++)
                #pragma unroll
                for (int nb = 0; nb < 4; nb++) {
                    mma16816(acc[mi][nb * 2 + 0], af[mi], bf[nb][0], bf[nb][2]);
                    mma16816(acc[mi][nb * 2 + 1], af[mi], bf[nb][1], bf[nb][3]);
                }
        }
    }
    __syncthreads();   // protect smem reuse for staging

    // ---- epilogue: stage (fp32, 128x260) then transformed write ----
    float* stage = (float*)smem;
    int gr = lane >> 2;
    int gc = (lane & 3) * 2;
    #pragma unroll
    for (int mi = 0; mi < 2; mi++)
        #pragma unroll
        for (int ni = 0; ni < 8; ni++) {
            int row = wm + mi * 16 + gr;
            int col = wn + ni * 8 + gc;
            *(float2*)&stage[row * STG_STRIDE + col] =
                make_float2(acc[mi][ni][0], acc[mi][ni][1]);
            *(float2*)&stage[(row + 8) * STG_STRIDE + col] =
                make_float2(acc[mi][ni][2], acc[mi][ni][3]);
        }
    __syncthreads();

    for (int i = tid; i < 128 * 64; i += 512) {
        int row = i >> 6, q = i & 63;
        int col = q * 4;
        int gcol = n0 + col;
        float4 b4 = *(const float4*)&g_bias[gcol];
        const float* s = &stage[row * STG_STRIDE + col];
        float4 v = make_float4(s[0] + b4.x, s[1] + b4.y, s[2] + b4.z, s[3] + b4.w);
        if (gcol >= PS_VAR && gcol < PS_VAR + 128) {   // s_var plane: exp(clip())
            v.x = __expf(fminf(fmaxf(v.x, -1.f), 1.f));
            v.y = __expf(fminf(fmaxf(v.y, -1.f), 1.f));
            v.z = __expf(fminf(fmaxf(v.z, -1.f), 1.f));
            v.w = __expf(fminf(fmaxf(v.w, -1.f), 1.f));
        }
        *(float4*)&g_C[(size_t)(m0 + row) * NTOTP + gcol] = v;
    }
}

// ---------------- scan ----------------
__device__ __forceinline__ float tanh_acc(float x) {
    float xc = fminf(fmaxf(x, -15.f), 15.f);
    float e = __expf(2.f * xc);
    return __fdividef(e - 1.f, e + 1.f);
}

struct Step { float sw, smu, svar, tw, m0, m1, r0, rs, r1; };

__device__ __forceinline__ Step load_step(int row, int chain, int j) {
    const float* base = g_C + (size_t)row * NTOTP;
    Step s;
    s.sw   = base[PS_W   + j];
    s.smu  = base[PS_MU  + j];
    s.svar = base[PS_VAR + j];
    s.tw   = base[PT_W   + chain];
    s.m0   = base[PT_MU0 + chain];
    s.m1   = base[PT_MU1 + chain];
    s.r0   = base[PT_D0  + chain];
    s.rs   = base[PT_SUM + chain];
    s.r1   = base[PT_D1  + chain];
    return s;
}

__device__ __forceinline__ void transform_t(const Step& s,
                                            float& v00, float& v01, float& v11) {
    float d0 = __expf(fminf(fmaxf(s.r0, -1.f), 1.f));
    float d1 = __expf(fminf(fmaxf(s.r1, -1.f), 1.f));
    v00 = d0; v11 = d1;
    v01 = 0.9f * tanh_acc(0.5f * s.rs) * sqrtf(d0 * d1);
}

__device__ __forceinline__ void merge2x2(
    float tmu0, float tmu1, float tv00, float tv01, float tv11,
    float nmu, float nvar, bool child,
    float& zeta, float& mu_new, float& var_new)
{
    float det  = tv00 * tv11 - tv01 * tv01;
    float idet = __fdividef(1.f, det);
    float a  = tv11 * idet;
    float bo = -tv01 * idet;
    float dd = tv00 * idet;
    float e0 = a  * tmu0 + bo * tmu1;
    float e1 = bo * tmu0 + dd * tmu1;
    float quad1 = e0 * e0 * tv00 + 2.f * e0 * e1 * tv01 + e1 * e1 * tv11;
    float zeta1 = -0.5f * (2.f * LOG2PI + __logf(det) + quad1);
    float l2   = __fdividef(1.f, nvar);
    float eta2 = nmu * l2;
    float zeta2 = -0.5f * (LOG2PI + __logf(nvar) + nmu * nmu * l2);
    float den, keep, es, la, iden;
    if (child) { den = dd + l2; iden = __fdividef(1.f, den); keep = e0; es = e1 + eta2; la = a  - bo * bo * iden; }
    else       { den = a  + l2; iden = __fdividef(1.f, den); keep = e1; es = e0 + eta2; la = dd - bo * bo * iden; }
    float eta_new = keep - bo * iden * es;
    var_new = __fdividef(1.f, la);
    mu_new  = var_new * eta_new;
    float zm = -0.5f * (LOG2PI - __logf(den) + es * es * iden);
    float zn = -0.5f * (LOG2PI - __logf(la)  + eta_new * eta_new * var_new);
    zeta = zeta1 + zeta2 - zm - zn;
}

__global__ __launch_bounds__(256) void scan_kernel(float* __restrict__ out)
{
    int chain = blockIdx.x * blockDim.x + threadIdx.x;
    if (chain >= LL2) return;
    int b = blockIdx.y;
    int j = chain % LL1;
    int row0 = b * TT;

    Step s0 = load_step(row0, chain, j);
    Step s1 = load_step(row0 + 1, chain, j);

    float v00, v01, v11;
    transform_t(s0, v00, v01, v11);
    float sc0, mu_c, var_c;
    merge2x2(s0.m0, s0.m1, v00, v01, v11, s0.smu, s0.svar, true, sc0, mu_c, var_c);

    float u00, u01, u11;
    transform_t(s1, u00, u01, u11);
    float sp0, mu_p, var_p;
    merge2x2(s1.m0, s1.m1, u00, u01, u11, mu_c, var_c, false, sp0, mu_p, var_p);

    out[(size_t)row0 * LL2 + chain] = sc0 + sp0 + s0.tw + s0.sw;

    Step cur = s1;
    for (int t = 1; t < TT; t++) {
        Step nxt;
        if (t + 1 < TT) nxt = load_step(row0 + t + 1, chain, j);

        float w00, w01, w11;
        transform_t(cur, w00, w01, w11);

        float vsum = var_p + cur.svar;
        float logv = __logf(vsum);
        float inv  = __fdividef(1.f, vsum);
        float diff = mu_p - cur.smu;
        float scale_c = -0.5f * (LOG2PI + logv + diff * diff * inv);
        float mu_c2  = (mu_p * cur.svar + cur.smu * var_p) * inv;
        float var_c2 = vsum - 0.5f * logv;

        float scale_p, mu_n, var_n;
        merge2x2(cur.m0, cur.m1, w00, w01, w11, mu_c2, var_c2, false, scale_p, mu_n, var_n);
        mu_p = mu_n; var_p = var_n;

        out[(size_t)(row0 + t) * LL2 + chain] = scale_c + scale_p + cur.tw + cur.sw;
        cur = nxt;
    }
}

// ---------------- launch ----------------
extern "C" void kernel_launch(void* const* d_in, const int* in_sizes, int n_in,
                              void* d_out, int out_size)
{
    const float* x      = (const float*)d_in[0];
    const float* Ws_w   = (const float*)d_in[1];
    const float* bs_w   = (const float*)d_in[2];
    const float* Ws_mu  = (const float*)d_in[3];
    const float* bs_mu  = (const float*)d_in[4];
    const float* Ws_var = (const float*)d_in[5];
    const float* bs_var = (const float*)d_in[6];
    const float* Wt_w   = (const float*)d_in[7];
    const float* bt_w   = (const float*)d_in[8];
    const float* Wt_mu  = (const float*)d_in[9];
    const float* bt_mu  = (const float*)d_in[10];
    const float* Wt_var = (const float*)d_in[11];
    const float* bt_var = (const float*)d_in[12];
    float* out = (float*)d_out;

    cudaFuncSetAttribute(gemm_tc, cudaFuncAttributeMaxDynamicSharedMemorySize, SMEM_BYTES);

    prep_all<<<dim3(84, 16, 10), dim3(32, 8)>>>(x, Ws_w, Ws_mu, Ws_var, Wt_w, Wt_mu, Wt_var,
                                                bs_w, bs_mu, bs_var, bt_w, bt_mu, bt_var);

    gemm_tc<<<dim3(32, NTILES), 512, SMEM_BYTES>>>();

    scan_kernel<<<dim3((LL2 + 255) / 256, BB), 256>>>(out);
}

// round 6
// speedup vs baseline: 1.3825x; 1.3825x over previous
#include <cuda_runtime.h>
#include <cuda_fp16.h>
#include <math.h>
#include <stdint.h>

// ---------------- problem constants ----------------
#define BB 16
#define TT 256
#define DD 512
#define LL1 51
#define MM (BB*TT)            // 4096
#define LL2 (LL1*LL1)         // 2601
#define KP 1024               // fp16 2-term split: [x_hi | x_lo] * [W_hi ; W_hi]
#define KC 64
#define NCH (KP/KC)           // 16
#define LOG2PI 1.8378770664093453f

// planar output layout (offsets multiples of 128)
#define NP_CH  2688
#define PS_W   0
#define PS_MU  128
#define PS_VAR 256
#define PT_W   384
#define PT_MU0 (PT_W  + NP_CH)   // 3072
#define PT_MU1 (PT_MU0 + NP_CH)  // 5760
#define PT_D0  (PT_MU1 + NP_CH)  // 8448
#define PT_SUM (PT_D0 + NP_CH)   // 11136
#define PT_D1  (PT_SUM + NP_CH)  // 13824
#define NTOT   (PT_D1 + NP_CH)   // 16512
#define NTILES 129               // 128-wide tiles

// ---------------- scratch (device globals) ----------------
__device__ __align__(256) __half g_Ap[(size_t)MM*KP];
__device__ __align__(256) __half g_Bp[(size_t)NTOT*KP];
__device__ __align__(256) float g_bias[NTOT];
__device__ __align__(256) float g_C[(size_t)MM*NTOT];

// ---------------- PTX helpers ----------------
__device__ __forceinline__ uint32_t smem_u32(const void* p) {
    uint32_t a;
    asm("{ .reg .u64 t; cvta.to.shared.u64 t, %1; cvt.u32.u64 %0, t; }" : "=r"(a) : "l"(p));
    return a;
}
__device__ __forceinline__ void cp_async16(uint32_t dst, const void* src) {
    asm volatile("cp.async.cg.shared.global [%0], [%1], 16;" :: "r"(dst), "l"(src));
}
#define CP_COMMIT() asm volatile("cp.async.commit_group;" ::: "memory")
#define CP_WAIT(n)  asm volatile("cp.async.wait_group %0;" :: "n"(n) : "memory")

__device__ __forceinline__ void ldmx4(uint32_t* r, uint32_t addr) {
    asm volatile("ldmatrix.sync.aligned.m8n8.x4.shared.b16 {%0,%1,%2,%3}, [%4];"
        : "=r"(r[0]), "=r"(r[1]), "=r"(r[2]), "=r"(r[3]) : "r"(addr));
}
__device__ __forceinline__ void mma16816(float* c, const uint32_t* a, uint32_t b0, uint32_t b1) {
    asm volatile("mma.sync.aligned.m16n8k16.row.col.f32.f16.f16.f32 "
        "{%0,%1,%2,%3}, {%4,%5,%6,%7}, {%8,%9}, {%0,%1,%2,%3};"
        : "+f"(c[0]), "+f"(c[1]), "+f"(c[2]), "+f"(c[3])
        : "r"(a[0]), "r"(a[1]), "r"(a[2]), "r"(a[3]), "r"(b0), "r"(b1));
}

// ---------------- fused prep: 9 W jobs + x-split + bias ----------------
// grid (84, 16, 10), block (32, 8)
__global__ void prep_all(const float* __restrict__ x,
    const float* __restrict__ Ws_w, const float* __restrict__ Ws_mu, const float* __restrict__ Ws_var,
    const float* __restrict__ Wt_w, const float* __restrict__ Wt_mu, const float* __restrict__ Wt_var,
    const float* __restrict__ bsw, const float* __restrict__ bsmu, const float* __restrict__ bsvar,
    const float* __restrict__ btw, const float* __restrict__ btmu, const float* __restrict__ btvar)
{
    int z = blockIdx.z;
    int tx = threadIdx.x, ty = threadIdx.y;
    int tid = ty * 32 + tx;

    if (z == 9) {
        int linb = blockIdx.y * gridDim.x + blockIdx.x;
        int nth  = gridDim.x * gridDim.y * 256;
        int gtid = linb * 256 + tid;
        // x -> [hi | lo] (fp16)
        for (int t = gtid; t < MM * DD; t += nth) {
            int m = t >> 9;
            int k = t & 511;
            float v = x[t];
            __half hi = __float2half(v);
            __half lo = __float2half(v - __half2float(hi));
            size_t base = (size_t)m * KP + k;
            g_Ap[base]       = hi;
            g_Ap[base + 512] = lo;
        }
        // bias
        for (int c = gtid; c < NTOT; c += nth) {
            float v = 0.f;
            if (c < PS_MU)        { if (c < LL1) v = bsw[c]; }
            else if (c < PS_VAR)  { int n = c - PS_MU;  if (n < LL1) v = bsmu[n]; }
            else if (c < PT_W)    { int n = c - PS_VAR; if (n < LL1) v = bsvar[n]; }
            else if (c < PT_MU0)  { int n = c - PT_W;   if (n < LL2) v = btw[n]; }
            else if (c < PT_MU1)  { int n = c - PT_MU0; if (n < LL2) v = btmu[2 * n]; }
            else if (c < PT_D0)   { int n = c - PT_MU1; if (n < LL2) v = btmu[2 * n + 1]; }
            else if (c < PT_SUM)  { int n = c - PT_D0;  if (n < LL2) v = btvar[4 * n]; }
            else if (c < PT_D1)   { int n = c - PT_SUM; if (n < LL2) v = btvar[4 * n + 1] + btvar[4 * n + 2]; }
            else                  { int n = c - PT_D1;  if (n < LL2) v = btvar[4 * n + 3]; }
            g_bias[c] = v;
        }
        return;
    }

    const float* W; int srcN, dstOff, nValid, colMul, colAdd, colAdd2, bx;
    switch (z) {
        case 0: W = Ws_w;   srcN = LL1;     dstOff = PS_W;   nValid = LL1; colMul = 1; colAdd = 0; colAdd2 = -1; bx = 4;  break;
        case 1: W = Ws_mu;  srcN = LL1;     dstOff = PS_MU;  nValid = LL1; colMul = 1; colAdd = 0; colAdd2 = -1; bx = 4;  break;
        case 2: W = Ws_var; srcN = LL1;     dstOff = PS_VAR; nValid = LL1; colMul = 1; colAdd = 0; colAdd2 = -1; bx = 4;  break;
        case 3: W = Wt_w;   srcN = LL2;     dstOff = PT_W;   nValid = LL2; colMul = 1; colAdd = 0; colAdd2 = -1; bx = 84; break;
        case 4: W = Wt_mu;  srcN = LL2 * 2; dstOff = PT_MU0; nValid = LL2; colMul = 2; colAdd = 0; colAdd2 = -1; bx = 84; break;
        case 5: W = Wt_mu;  srcN = LL2 * 2; dstOff = PT_MU1; nValid = LL2; colMul = 2; colAdd = 1; colAdd2 = -1; bx = 84; break;
        case 6: W = Wt_var; srcN = LL2 * 4; dstOff = PT_D0;  nValid = LL2; colMul = 4; colAdd = 0; colAdd2 = -1; bx = 84; break;
        case 7: W = Wt_var; srcN = LL2 * 4; dstOff = PT_SUM; nValid = LL2; colMul = 4; colAdd = 1; colAdd2 = 2;  bx = 84; break;
        default:W = Wt_var; srcN = LL2 * 4; dstOff = PT_D1;  nValid = LL2; colMul = 4; colAdd = 3; colAdd2 = -1; bx = 84; break;
    }
    if ((int)blockIdx.x >= bx) return;

    __shared__ float tile[32][33];
    int n = blockIdx.x * 32 + tx;
    #pragma unroll
    for (int i = 0; i < 4; i++) {
        int k = blockIdx.y * 32 + ty + i * 8;
        float v = 0.f;
        if (n < nValid) {
            v = W[(size_t)k * srcN + n * colMul + colAdd];
            if (colAdd2 >= 0) v += W[(size_t)k * srcN + n * colMul + colAdd2];
        }
        tile[ty + i * 8][tx] = v;
    }
    __syncthreads();
    #pragma unroll
    for (int i = 0; i < 4; i++) {
        int n2 = blockIdx.x * 32 + ty + i * 8;
        int k2 = blockIdx.y * 32 + tx;
        float v = tile[tx][ty + i * 8];
        __half hi = __float2half(v);
        __half* row = g_Bp + (size_t)(dstOff + n2) * KP;
        row[k2]       = hi;
        row[512 + k2] = hi;    // same W_hi in both halves: result = (x_hi + x_lo) * W_hi
    }
}

// ---------------- HMMA GEMM: 128x128 CTA, 256 threads, KC=64, 3-stage ------
#define TILE_STRIDE 72
#define HALF_BYTES 18432               // 128*144
#define BUF_BYTES 36864
#define SMEM_BYTES (3*BUF_BYTES)       // 110592
#define STG_STRIDE 132

__device__ __forceinline__ void issue_tile(uint32_t dstBase,
                                           const __half* __restrict__ src,
                                           int row0, int kc, int tid) {
    #pragma unroll
    for (int i = 0; i < 4; i++) {
        int ci  = i * 256 + tid;
        int r   = ci >> 3;
        int c16 = ci & 7;
        uint32_t dst = dstBase + (uint32_t)(r * (TILE_STRIDE * 2) + c16 * 16);
        cp_async16(dst, src + (size_t)(row0 + r) * KP + kc + c16 * 8);
    }
}

__global__ void __launch_bounds__(256, 2) gemm_tc()
{
    extern __shared__ char smem[];
    uint32_t sbase = smem_u32(smem);
    int tid = threadIdx.x, wid = tid >> 5, lane = tid & 31;
    int m0 = blockIdx.x * 128;
    int n0 = blockIdx.y * 128;

    int wm = (wid & 3) * 32;
    int wn = (wid >> 2) * 64;
    int lr = lane & 15;
    int lc = (lane >> 4) * 8;

    float acc[2][8][4];
    #pragma unroll
    for (int mi = 0; mi < 2; mi++)
        #pragma unroll
        for (int ni = 0; ni < 8; ni++)
            #pragma unroll
            for (int q = 0; q < 4; q++) acc[mi][ni][q] = 0.f;

    issue_tile(sbase,              g_Ap, m0, 0, tid);
    issue_tile(sbase + HALF_BYTES, g_Bp, n0, 0, tid);
    CP_COMMIT();
    issue_tile(sbase + BUF_BYTES,              g_Ap, m0, KC, tid);
    issue_tile(sbase + BUF_BYTES + HALF_BYTES, g_Bp, n0, KC, tid);
    CP_COMMIT();

    for (int c = 0; c < NCH; c++) {
        if (c + 1 < NCH) { CP_WAIT(1); } else { CP_WAIT(0); }
        __syncthreads();
        if (c + 2 < NCH) {
            uint32_t nb = sbase + (uint32_t)(((c + 2) % 3) * BUF_BYTES);
            issue_tile(nb,              g_Ap, m0, (c + 2) * KC, tid);
            issue_tile(nb + HALF_BYTES, g_Bp, n0, (c + 2) * KC, tid);
            CP_COMMIT();
        }
        uint32_t aBase = sbase + (uint32_t)((c % 3) * BUF_BYTES);
        uint32_t bBase = aBase + HALF_BYTES;
        #pragma unroll
        for (int ks = 0; ks < 4; ks++) {
            uint32_t af[2][4];
            #pragma unroll
            for (int mi = 0; mi < 2; mi++)
                ldmx4(af[mi], aBase + (uint32_t)(((wm + mi * 16 + lr) * TILE_STRIDE
                                                  + ks * 16 + lc) * 2));
            uint32_t bf[4][4];
            #pragma unroll
            for (int nb = 0; nb < 4; nb++)
                ldmx4(bf[nb], bBase + (uint32_t)(((wn + nb * 16 + lr) * TILE_STRIDE
                                                  + ks * 16 + lc) * 2));
            #pragma unroll
            for (int mi = 0; mi < 2; mi++)
                #pragma unroll
                for (int nb = 0; nb < 4; nb++) {
                    mma16816(acc[mi][nb * 2 + 0], af[mi], bf[nb][0], bf[nb][2]);
                    mma16816(acc[mi][nb * 2 + 1], af[mi], bf[nb][1], bf[nb][3]);
                }
        }
    }
    __syncthreads();

    // epilogue: stage fp32 then transformed write
    float* stage = (float*)smem;
    int gr = lane >> 2;
    int gc = (lane & 3) * 2;
    #pragma unroll
    for (int mi = 0; mi < 2; mi++)
        #pragma unroll
        for (int ni = 0; ni < 8; ni++) {
            int row = wm + mi * 16 + gr;
            int col = wn + ni * 8 + gc;
            *(float2*)&stage[row * STG_STRIDE + col] =
                make_float2(acc[mi][ni][0], acc[mi][ni][1]);
            *(float2*)&stage[(row + 8) * STG_STRIDE + col] =
                make_float2(acc[mi][ni][2], acc[mi][ni][3]);
        }
    __syncthreads();

    bool isv = (n0 == PS_VAR);
    for (int i = tid; i < 128 * 32; i += 256) {
        int row = i >> 5, q = i & 31;
        int col = q * 4;
        float4 b4 = *(const float4*)&g_bias[n0 + col];
        const float* s = &stage[row * STG_STRIDE + col];
        float4 v = make_float4(s[0] + b4.x, s[1] + b4.y, s[2] + b4.z, s[3] + b4.w);
        if (isv) {
            v.x = __expf(fminf(fmaxf(v.x, -1.f), 1.f));
            v.y = __expf(fminf(fmaxf(v.y, -1.f), 1.f));
            v.z = __expf(fminf(fmaxf(v.z, -1.f), 1.f));
            v.w = __expf(fminf(fmaxf(v.w, -1.f), 1.f));
        }
        *(float4*)&g_C[(size_t)(m0 + row) * NTOT + n0 + col] = v;
    }
}

// ---------------- scan ----------------
__device__ __forceinline__ float tanh_acc(float x) {
    float xc = fminf(fmaxf(x, -15.f), 15.f);
    float e = __expf(2.f * xc);
    return __fdividef(e - 1.f, e + 1.f);
}

struct Step { float sw, smu, svar, tw, m0, m1, r0, rs, r1; };

__device__ __forceinline__ Step load_step(int row, int chain, int j) {
    const float* base = g_C + (size_t)row * NTOT;
    Step s;
    s.sw   = base[PS_W   + j];
    s.smu  = base[PS_MU  + j];
    s.svar = base[PS_VAR + j];
    s.tw   = base[PT_W   + chain];
    s.m0   = base[PT_MU0 + chain];
    s.m1   = base[PT_MU1 + chain];
    s.r0   = base[PT_D0  + chain];
    s.rs   = base[PT_SUM + chain];
    s.r1   = base[PT_D1  + chain];
    return s;
}

__device__ __forceinline__ void transform_t(const Step& s,
                                            float& v00, float& v01, float& v11) {
    float d0 = __expf(fminf(fmaxf(s.r0, -1.f), 1.f));
    float d1 = __expf(fminf(fmaxf(s.r1, -1.f), 1.f));
    v00 = d0; v11 = d1;
    v01 = 0.9f * tanh_acc(0.5f * s.rs) * sqrtf(d0 * d1);
}

__device__ __forceinline__ void merge2x2(
    float tmu0, float tmu1, float tv00, float tv01, float tv11,
    float nmu, float nvar, bool child,
    float& zeta, float& mu_new, float& var_new)
{
    float det  = tv00 * tv11 - tv01 * tv01;
    float idet = __fdividef(1.f, det);
    float a  = tv11 * idet;
    float bo = -tv01 * idet;
    float dd = tv00 * idet;
    float e0 = a  * tmu0 + bo * tmu1;
    float e1 = bo * tmu0 + dd * tmu1;
    float quad1 = e0 * e0 * tv00 + 2.f * e0 * e1 * tv01 + e1 * e1 * tv11;
    float zeta1 = -0.5f * (2.f * LOG2PI + __logf(det) + quad1);
    float l2   = __fdividef(1.f, nvar);
    float eta2 = nmu * l2;
    float zeta2 = -0.5f * (LOG2PI + __logf(nvar) + nmu * nmu * l2);
    float den, keep, es, la, iden;
    if (child) { den = dd + l2; iden = __fdividef(1.f, den); keep = e0; es = e1 + eta2; la = a  - bo * bo * iden; }
    else       { den = a  + l2; iden = __fdividef(1.f, den); keep = e1; es = e0 + eta2; la = dd - bo * bo * iden; }
    float eta_new = keep - bo * iden * es;
    var_new = __fdividef(1.f, la);
    mu_new  = var_new * eta_new;
    float zm = -0.5f * (LOG2PI - __logf(den) + es * es * iden);
    float zn = -0.5f * (LOG2PI - __logf(la)  + eta_new * eta_new * var_new);
    zeta = zeta1 + zeta2 - zm - zn;
}

__global__ __launch_bounds__(256) void scan_kernel(float* __restrict__ out)
{
    int chain = blockIdx.x * blockDim.x + threadIdx.x;
    if (chain >= LL2) return;
    int b = blockIdx.y;
    int j = chain % LL1;
    int row0 = b * TT;

    Step s0 = load_step(row0, chain, j);
    Step s1 = load_step(row0 + 1, chain, j);

    float v00, v01, v11;
    transform_t(s0, v00, v01, v11);
    float sc0, mu_c, var_c;
    merge2x2(s0.m0, s0.m1, v00, v01, v11, s0.smu, s0.svar, true, sc0, mu_c, var_c);

    float u00, u01, u11;
    transform_t(s1, u00, u01, u11);
    float sp0, mu_p, var_p;
    merge2x2(s1.m0, s1.m1, u00, u01, u11, mu_c, var_c, false, sp0, mu_p, var_p);

    out[(size_t)row0 * LL2 + chain] = sc0 + sp0 + s0.tw + s0.sw;

    Step cur = s1;
    for (int t = 1; t < TT; t++) {
        Step nxt;
        if (t + 1 < TT) nxt = load_step(row0 + t + 1, chain, j);

        float w00, w01, w11;
        transform_t(cur, w00, w01, w11);

        float vsum = var_p + cur.svar;
        float logv = __logf(vsum);
        float inv  = __fdividef(1.f, vsum);
        float diff = mu_p - cur.smu;
        float scale_c = -0.5f * (LOG2PI + logv + diff * diff * inv);
        float mu_c2  = (mu_p * cur.svar + cur.smu * var_p) * inv;
        float var_c2 = vsum - 0.5f * logv;

        float scale_p, mu_n, var_n;
        merge2x2(cur.m0, cur.m1, w00, w01, w11, mu_c2, var_c2, false, scale_p, mu_n, var_n);
        mu_p = mu_n; var_p = var_n;

        out[(size_t)(row0 + t) * LL2 + chain] = scale_c + scale_p + cur.tw + cur.sw;
        cur = nxt;
    }
}

// ---------------- launch ----------------
extern "C" void kernel_launch(void* const* d_in, const int* in_sizes, int n_in,
                              void* d_out, int out_size)
{
    const float* x      = (const float*)d_in[0];
    const float* Ws_w   = (const float*)d_in[1];
    const float* bs_w   = (const float*)d_in[2];
    const float* Ws_mu  = (const float*)d_in[3];
    const float* bs_mu  = (const float*)d_in[4];
    const float* Ws_var = (const float*)d_in[5];
    const float* bs_var = (const float*)d_in[6];
    const float* Wt_w   = (const float*)d_in[7];
    const float* bt_w   = (const float*)d_in[8];
    const float* Wt_mu  = (const float*)d_in[9];
    const float* bt_mu  = (const float*)d_in[10];
    const float* Wt_var = (const float*)d_in[11];
    const float* bt_var = (const float*)d_in[12];
    float* out = (float*)d_out;

    cudaFuncSetAttribute(gemm_tc, cudaFuncAttributeMaxDynamicSharedMemorySize, SMEM_BYTES);

    prep_all<<<dim3(84, 16, 10), dim3(32, 8)>>>(x, Ws_w, Ws_mu, Ws_var, Wt_w, Wt_mu, Wt_var,
                                                bs_w, bs_mu, bs_var, bt_w, bt_mu, bt_var);

    gemm_tc<<<dim3(32, NTILES), 256, SMEM_BYTES>>>();

    scan_kernel<<<dim3((LL2 + 255) / 256, BB), 256>>>(out);
}

// round 7
// speedup vs baseline: 2.0080x; 1.4525x over previous
#include <cuda_runtime.h>
#include <cuda_fp16.h>
#include <math.h>
#include <stdint.h>

// ---------------- problem constants ----------------
#define BB 16
#define TT 256
#define DD 512
#define LL1 51
#define MM (BB*TT)            // 4096
#define LL2 (LL1*LL1)         // 2601
#define NCHAINS (BB*LL2)      // 41616
#define KP 512                // plain fp16 GEMM
#define KC 64
#define NCH (KP/KC)           // 8
#define LOG2PI 1.8378770664093453f

// planar output layout (offsets multiples of 128)
#define NP_CH  2688
#define PS_W   0
#define PS_MU  128
#define PS_VAR 256
#define PT_W   384
#define PT_MU0 (PT_W  + NP_CH)   // 3072
#define PT_MU1 (PT_MU0 + NP_CH)  // 5760
#define PT_D0  (PT_MU1 + NP_CH)  // 8448
#define PT_SUM (PT_D0 + NP_CH)   // 11136
#define PT_D1  (PT_SUM + NP_CH)  // 13824
#define NTOT   (PT_D1 + NP_CH)   // 16512
#define NTILES 129               // 128-wide tiles

// ---------------- scratch (device globals) ----------------
__device__ __align__(256) __half g_Ap[(size_t)MM*KP];
__device__ __align__(256) __half g_Bp[(size_t)NTOT*KP];
__device__ __align__(256) float g_bias[NTOT];
__device__ __align__(256) float g_C[(size_t)MM*NTOT];

// ---------------- PTX helpers ----------------
__device__ __forceinline__ uint32_t smem_u32(const void* p) {
    uint32_t a;
    asm("{ .reg .u64 t; cvta.to.shared.u64 t, %1; cvt.u32.u64 %0, t; }" : "=r"(a) : "l"(p));
    return a;
}
__device__ __forceinline__ void cp_async16(uint32_t dst, const void* src) {
    asm volatile("cp.async.cg.shared.global [%0], [%1], 16;" :: "r"(dst), "l"(src));
}
#define CP_COMMIT() asm volatile("cp.async.commit_group;" ::: "memory")
#define CP_WAIT(n)  asm volatile("cp.async.wait_group %0;" :: "n"(n) : "memory")

__device__ __forceinline__ void ldmx4(uint32_t* r, uint32_t addr) {
    asm volatile("ldmatrix.sync.aligned.m8n8.x4.shared.b16 {%0,%1,%2,%3}, [%4];"
        : "=r"(r[0]), "=r"(r[1]), "=r"(r[2]), "=r"(r[3]) : "r"(addr));
}
__device__ __forceinline__ void mma16816(float* c, const uint32_t* a, uint32_t b0, uint32_t b1) {
    asm volatile("mma.sync.aligned.m16n8k16.row.col.f32.f16.f16.f32 "
        "{%0,%1,%2,%3}, {%4,%5,%6,%7}, {%8,%9}, {%0,%1,%2,%3};"
        : "+f"(c[0]), "+f"(c[1]), "+f"(c[2]), "+f"(c[3])
        : "r"(a[0]), "r"(a[1]), "r"(a[2]), "r"(a[3]), "r"(b0), "r"(b1));
}

// ---------------- fused prep: 9 W jobs + x-convert + bias ----------------
// grid (84, 16, 10), block (32, 8)
__global__ void prep_all(const float* __restrict__ x,
    const float* __restrict__ Ws_w, const float* __restrict__ Ws_mu, const float* __restrict__ Ws_var,
    const float* __restrict__ Wt_w, const float* __restrict__ Wt_mu, const float* __restrict__ Wt_var,
    const float* __restrict__ bsw, const float* __restrict__ bsmu, const float* __restrict__ bsvar,
    const float* __restrict__ btw, const float* __restrict__ btmu, const float* __restrict__ btvar)
{
    int z = blockIdx.z;
    int tx = threadIdx.x, ty = threadIdx.y;
    int tid = ty * 32 + tx;

    if (z == 9) {
        int linb = blockIdx.y * gridDim.x + blockIdx.x;
        int nth  = gridDim.x * gridDim.y * 256;
        int gtid = linb * 256 + tid;
        for (int t = gtid; t < MM * DD; t += nth)
            g_Ap[t] = __float2half(x[t]);
        for (int c = gtid; c < NTOT; c += nth) {
            float v = 0.f;
            if (c < PS_MU)        { if (c < LL1) v = bsw[c]; }
            else if (c < PS_VAR)  { int n = c - PS_MU;  if (n < LL1) v = bsmu[n]; }
            else if (c < PT_W)    { int n = c - PS_VAR; if (n < LL1) v = bsvar[n]; }
            else if (c < PT_MU0)  { int n = c - PT_W;   if (n < LL2) v = btw[n]; }
            else if (c < PT_MU1)  { int n = c - PT_MU0; if (n < LL2) v = btmu[2 * n]; }
            else if (c < PT_D0)   { int n = c - PT_MU1; if (n < LL2) v = btmu[2 * n + 1]; }
            else if (c < PT_SUM)  { int n = c - PT_D0;  if (n < LL2) v = btvar[4 * n]; }
            else if (c < PT_D1)   { int n = c - PT_SUM; if (n < LL2) v = btvar[4 * n + 1] + btvar[4 * n + 2]; }
            else                  { int n = c - PT_D1;  if (n < LL2) v = btvar[4 * n + 3]; }
            g_bias[c] = v;
        }
        return;
    }

    const float* W; int srcN, dstOff, nValid, colMul, colAdd, colAdd2, bx;
    switch (z) {
        case 0: W = Ws_w;   srcN = LL1;     dstOff = PS_W;   nValid = LL1; colMul = 1; colAdd = 0; colAdd2 = -1; bx = 4;  break;
        case 1: W = Ws_mu;  srcN = LL1;     dstOff = PS_MU;  nValid = LL1; colMul = 1; colAdd = 0; colAdd2 = -1; bx = 4;  break;
        case 2: W = Ws_var; srcN = LL1;     dstOff = PS_VAR; nValid = LL1; colMul = 1; colAdd = 0; colAdd2 = -1; bx = 4;  break;
        case 3: W = Wt_w;   srcN = LL2;     dstOff = PT_W;   nValid = LL2; colMul = 1; colAdd = 0; colAdd2 = -1; bx = 84; break;
        case 4: W = Wt_mu;  srcN = LL2 * 2; dstOff = PT_MU0; nValid = LL2; colMul = 2; colAdd = 0; colAdd2 = -1; bx = 84; break;
        case 5: W = Wt_mu;  srcN = LL2 * 2; dstOff = PT_MU1; nValid = LL2; colMul = 2; colAdd = 1; colAdd2 = -1; bx = 84; break;
        case 6: W = Wt_var; srcN = LL2 * 4; dstOff = PT_D0;  nValid = LL2; colMul = 4; colAdd = 0; colAdd2 = -1; bx = 84; break;
        case 7: W = Wt_var; srcN = LL2 * 4; dstOff = PT_SUM; nValid = LL2; colMul = 4; colAdd = 1; colAdd2 = 2;  bx = 84; break;
        default:W = Wt_var; srcN = LL2 * 4; dstOff = PT_D1;  nValid = LL2; colMul = 4; colAdd = 3; colAdd2 = -1; bx = 84; break;
    }
    if ((int)blockIdx.x >= bx) return;

    __shared__ float tile[32][33];
    int n = blockIdx.x * 32 + tx;
    #pragma unroll
    for (int i = 0; i < 4; i++) {
        int k = blockIdx.y * 32 + ty + i * 8;
        float v = 0.f;
        if (n < nValid) {
            v = W[(size_t)k * srcN + n * colMul + colAdd];
            if (colAdd2 >= 0) v += W[(size_t)k * srcN + n * colMul + colAdd2];
        }
        tile[ty + i * 8][tx] = v;
    }
    __syncthreads();
    #pragma unroll
    for (int i = 0; i < 4; i++) {
        int n2 = blockIdx.x * 32 + ty + i * 8;
        int k2 = blockIdx.y * 32 + tx;
        g_Bp[(size_t)(dstOff + n2) * KP + k2] = __float2half(tile[tx][ty + i * 8]);
    }
}

// ---------------- HMMA GEMM: 128x128 CTA, 256 threads, KC=64, 3-stage ------
#define TILE_STRIDE 72
#define HALF_BYTES 18432               // 128*144
#define BUF_BYTES 36864
#define SMEM_BYTES (3*BUF_BYTES)       // 110592
#define STG_STRIDE 132

__device__ __forceinline__ void issue_tile(uint32_t dstBase,
                                           const __half* __restrict__ src,
                                           int row0, int kc, int tid) {
    #pragma unroll
    for (int i = 0; i < 4; i++) {
        int ci  = i * 256 + tid;
        int r   = ci >> 3;
        int c16 = ci & 7;
        uint32_t dst = dstBase + (uint32_t)(r * (TILE_STRIDE * 2) + c16 * 16);
        cp_async16(dst, src + (size_t)(row0 + r) * KP + kc + c16 * 8);
    }
}

__global__ void __launch_bounds__(256, 2) gemm_tc()
{
    extern __shared__ char smem[];
    uint32_t sbase = smem_u32(smem);
    int tid = threadIdx.x, wid = tid >> 5, lane = tid & 31;
    int m0 = blockIdx.x * 128;
    int n0 = blockIdx.y * 128;

    int wm = (wid & 3) * 32;
    int wn = (wid >> 2) * 64;
    int lr = lane & 15;
    int lc = (lane >> 4) * 8;

    float acc[2][8][4];
    #pragma unroll
    for (int mi = 0; mi < 2; mi++)
        #pragma unroll
        for (int ni = 0; ni < 8; ni++)
            #pragma unroll
            for (int q = 0; q < 4; q++) acc[mi][ni][q] = 0.f;

    issue_tile(sbase,              g_Ap, m0, 0, tid);
    issue_tile(sbase + HALF_BYTES, g_Bp, n0, 0, tid);
    CP_COMMIT();
    issue_tile(sbase + BUF_BYTES,              g_Ap, m0, KC, tid);
    issue_tile(sbase + BUF_BYTES + HALF_BYTES, g_Bp, n0, KC, tid);
    CP_COMMIT();

    for (int c = 0; c < NCH; c++) {
        if (c + 1 < NCH) { CP_WAIT(1); } else { CP_WAIT(0); }
        __syncthreads();
        if (c + 2 < NCH) {
            uint32_t nb = sbase + (uint32_t)(((c + 2) % 3) * BUF_BYTES);
            issue_tile(nb,              g_Ap, m0, (c + 2) * KC, tid);
            issue_tile(nb + HALF_BYTES, g_Bp, n0, (c + 2) * KC, tid);
            CP_COMMIT();
        }
        uint32_t aBase = sbase + (uint32_t)((c % 3) * BUF_BYTES);
        uint32_t bBase = aBase + HALF_BYTES;
        #pragma unroll
        for (int ks = 0; ks < 4; ks++) {
            uint32_t af[2][4];
            #pragma unroll
            for (int mi = 0; mi < 2; mi++)
                ldmx4(af[mi], aBase + (uint32_t)(((wm + mi * 16 + lr) * TILE_STRIDE
                                                  + ks * 16 + lc) * 2));
            uint32_t bf[4][4];
            #pragma unroll
            for (int nb = 0; nb < 4; nb++)
                ldmx4(bf[nb], bBase + (uint32_t)(((wn + nb * 16 + lr) * TILE_STRIDE
                                                  + ks * 16 + lc) * 2));
            #pragma unroll
            for (int mi = 0; mi < 2; mi++)
                #pragma unroll
                for (int nb = 0; nb < 4; nb++) {
                    mma16816(acc[mi][nb * 2 + 0], af[mi], bf[nb][0], bf[nb][2]);
                    mma16816(acc[mi][nb * 2 + 1], af[mi], bf[nb][1], bf[nb][3]);
                }
        }
    }
    __syncthreads();

    // epilogue: stage fp32 then transformed write
    float* stage = (float*)smem;
    int gr = lane >> 2;
    int gc = (lane & 3) * 2;
    #pragma unroll
    for (int mi = 0; mi < 2; mi++)
        #pragma unroll
        for (int ni = 0; ni < 8; ni++) {
            int row = wm + mi * 16 + gr;
            int col = wn + ni * 8 + gc;
            *(float2*)&stage[row * STG_STRIDE + col] =
                make_float2(acc[mi][ni][0], acc[mi][ni][1]);
            *(float2*)&stage[(row + 8) * STG_STRIDE + col] =
                make_float2(acc[mi][ni][2], acc[mi][ni][3]);
        }
    __syncthreads();

    bool isv = (n0 == PS_VAR);
    for (int i = tid; i < 128 * 32; i += 256) {
        int row = i >> 5, q = i & 31;
        int col = q * 4;
        float4 b4 = *(const float4*)&g_bias[n0 + col];
        const float* s = &stage[row * STG_STRIDE + col];
        float4 v = make_float4(s[0] + b4.x, s[1] + b4.y, s[2] + b4.z, s[3] + b4.w);
        if (isv) {
            v.x = __expf(fminf(fmaxf(v.x, -1.f), 1.f));
            v.y = __expf(fminf(fmaxf(v.y, -1.f), 1.f));
            v.z = __expf(fminf(fmaxf(v.z, -1.f), 1.f));
            v.w = __expf(fminf(fmaxf(v.w, -1.f), 1.f));
        }
        *(float4*)&g_C[(size_t)(m0 + row) * NTOT + n0 + col] = v;
    }
}

// ---------------- scan ----------------
__device__ __forceinline__ float tanh_acc(float x) {
    float xc = fminf(fmaxf(x, -15.f), 15.f);
    float e = __expf(2.f * xc);
    return __fdividef(e - 1.f, e + 1.f);
}

struct Step { float sw, smu, svar, tw, m0, m1, r0, rs, r1; };

__device__ __forceinline__ Step load_step(int row, int chain, int j) {
    const float* base = g_C + (size_t)row * NTOT;
    Step s;
    s.sw   = base[PS_W   + j];
    s.smu  = base[PS_MU  + j];
    s.svar = base[PS_VAR + j];
    s.tw   = base[PT_W   + chain];
    s.m0   = base[PT_MU0 + chain];
    s.m1   = base[PT_MU1 + chain];
    s.r0   = base[PT_D0  + chain];
    s.rs   = base[PT_SUM + chain];
    s.r1   = base[PT_D1  + chain];
    return s;
}

__device__ __forceinline__ void transform_t(const Step& s,
                                            float& v00, float& v01, float& v11) {
    float d0 = __expf(fminf(fmaxf(s.r0, -1.f), 1.f));
    float d1 = __expf(fminf(fmaxf(s.r1, -1.f), 1.f));
    v00 = d0; v11 = d1;
    v01 = 0.9f * tanh_acc(0.5f * s.rs) * sqrtf(d0 * d1);
}

__device__ __forceinline__ void merge2x2(
    float tmu0, float tmu1, float tv00, float tv01, float tv11,
    float nmu, float nvar, bool child,
    float& zeta, float& mu_new, float& var_new)
{
    float det  = tv00 * tv11 - tv01 * tv01;
    float idet = __fdividef(1.f, det);
    float a  = tv11 * idet;
    float bo = -tv01 * idet;
    float dd = tv00 * idet;
    float e0 = a  * tmu0 + bo * tmu1;
    float e1 = bo * tmu0 + dd * tmu1;
    float quad1 = e0 * e0 * tv00 + 2.f * e0 * e1 * tv01 + e1 * e1 * tv11;
    float zeta1 = -0.5f * (2.f * LOG2PI + __logf(det) + quad1);
    float l2   = __fdividef(1.f, nvar);
    float eta2 = nmu * l2;
    float zeta2 = -0.5f * (LOG2PI + __logf(nvar) + nmu * nmu * l2);
    float den, keep, es, la, iden;
    if (child) { den = dd + l2; iden = __fdividef(1.f, den); keep = e0; es = e1 + eta2; la = a  - bo * bo * iden; }
    else       { den = a  + l2; iden = __fdividef(1.f, den); keep = e1; es = e0 + eta2; la = dd - bo * bo * iden; }
    float eta_new = keep - bo * iden * es;
    var_new = __fdividef(1.f, la);
    mu_new  = var_new * eta_new;
    float zm = -0.5f * (LOG2PI - __logf(den) + es * es * iden);
    float zn = -0.5f * (LOG2PI - __logf(la)  + eta_new * eta_new * var_new);
    zeta = zeta1 + zeta2 - zm - zn;
}

// single-wave: 145 CTAs x 288 threads >= 41616 chains
__global__ __launch_bounds__(288) void scan_kernel(float* __restrict__ out)
{
    int q = blockIdx.x * 288 + threadIdx.x;
    if (q >= NCHAINS) return;
    int b = q / LL2;
    int chain = q - b * LL2;
    int j = chain % LL1;
    int row0 = b * TT;

    Step s0 = load_step(row0, chain, j);
    Step s1 = load_step(row0 + 1, chain, j);

    float v00, v01, v11;
    transform_t(s0, v00, v01, v11);
    float sc0, mu_c, var_c;
    merge2x2(s0.m0, s0.m1, v00, v01, v11, s0.smu, s0.svar, true, sc0, mu_c, var_c);

    float u00, u01, u11;
    transform_t(s1, u00, u01, u11);
    float sp0, mu_p, var_p;
    merge2x2(s1.m0, s1.m1, u00, u01, u11, mu_c, var_c, false, sp0, mu_p, var_p);

    out[(size_t)row0 * LL2 + chain] = sc0 + sp0 + s0.tw + s0.sw;

    Step cur = s1;
    for (int t = 1; t < TT; t++) {
        Step nxt;
        if (t + 1 < TT) nxt = load_step(row0 + t + 1, chain, j);

        float w00, w01, w11;
        transform_t(cur, w00, w01, w11);

        float vsum = var_p + cur.svar;
        float logv = __logf(vsum);
        float inv  = __fdividef(1.f, vsum);
        float diff = mu_p - cur.smu;
        float scale_c = -0.5f * (LOG2PI + logv + diff * diff * inv);
        float mu_c2  = (mu_p * cur.svar + cur.smu * var_p) * inv;
        float var_c2 = vsum - 0.5f * logv;

        float scale_p, mu_n, var_n;
        merge2x2(cur.m0, cur.m1, w00, w01, w11, mu_c2, var_c2, false, scale_p, mu_n, var_n);
        mu_p = mu_n; var_p = var_n;

        out[(size_t)(row0 + t) * LL2 + chain] = scale_c + scale_p + cur.tw + cur.sw;
        cur = nxt;
    }
}

// ---------------- launch ----------------
extern "C" void kernel_launch(void* const* d_in, const int* in_sizes, int n_in,
                              void* d_out, int out_size)
{
    const float* x      = (const float*)d_in[0];
    const float* Ws_w   = (const float*)d_in[1];
    const float* bs_w   = (const float*)d_in[2];
    const float* Ws_mu  = (const float*)d_in[3];
    const float* bs_mu  = (const float*)d_in[4];
    const float* Ws_var = (const float*)d_in[5];
    const float* bs_var = (const float*)d_in[6];
    const float* Wt_w   = (const float*)d_in[7];
    const float* bt_w   = (const float*)d_in[8];
    const float* Wt_mu  = (const float*)d_in[9];
    const float* bt_mu  = (const float*)d_in[10];
    const float* Wt_var = (const float*)d_in[11];
    const float* bt_var = (const float*)d_in[12];
    float* out = (float*)d_out;

    cudaFuncSetAttribute(gemm_tc, cudaFuncAttributeMaxDynamicSharedMemorySize, SMEM_BYTES);

    prep_all<<<dim3(84, 16, 10), dim3(32, 8)>>>(x, Ws_w, Ws_mu, Ws_var, Wt_w, Wt_mu, Wt_var,
                                                bs_w, bs_mu, bs_var, bt_w, bt_mu, bt_var);

    gemm_tc<<<dim3(32, NTILES), 256, SMEM_BYTES>>>();

    scan_kernel<<<(NCHAINS + 287) / 288, 288>>>(out);
}